// round 8
// baseline (speedup 1.0000x reference)
#include <cuda_runtime.h>
#include <cstdint>

#define IMG_H 512
#define IMG_W 512
#define TILE_W 64
#define TILE_H 16
#define HALO 5
#define IN_W (TILE_W + 2*HALO)   // 74 logical halo columns
#define IN_H (TILE_H + 2*HALO)   // 26
#define SSTRIDE 80               // padded smem row stride (floats) for s1/s2
#define S2STRIDE 80              // mid plane stride in float2 units
#define NTHREADS 256
#define MM_BLOCKS 1184

typedef unsigned long long ull;

// Normalized Gaussian taps: g[k] = exp(-(k - 11/2)^2 / (2*1.5^2)) / sum, k=0..10.
// Center at 5.5 => ASYMMETRIC: w[k] == w[11-k] for k>=1, w[0] unique smallest.
__host__ __device__ __forceinline__ constexpr float Wc(int k) {
    return (k == 0)            ? 3.2030000e-04f
         : (k == 1 || k == 10) ? 2.9556400e-03f
         : (k == 2 || k == 9 ) ? 1.7487660e-02f
         : (k == 3 || k == 8 ) ? 6.6342400e-02f
         : (k == 4 || k == 7 ) ? 1.6137290e-01f
         :                       2.5168140e-01f;   // k == 5 || k == 6
}
// unique-weight index for k
__host__ __device__ __forceinline__ constexpr int Widx(int k) {
    return (k == 0)            ? 0
         : (k == 1 || k == 10) ? 1
         : (k == 2 || k == 9 ) ? 2
         : (k == 3 || k == 8 ) ? 3
         : (k == 4 || k == 7 ) ? 4
         :                       5;
}

// ---- f32x2 packed helpers ----
__device__ __forceinline__ ull pack2(float lo, float hi) {
    ull r;
    asm("mov.b64 %0, {%1, %2};" : "=l"(r) : "f"(lo), "f"(hi));
    return r;
}
__device__ __forceinline__ void unpack2(float& lo, float& hi, ull v) {
    asm("mov.b64 {%0, %1}, %2;" : "=f"(lo), "=f"(hi) : "l"(v));
}
__device__ __forceinline__ ull fma2(ull a, ull b, ull c) {
    ull d;
    asm("fma.rn.f32x2 %0, %1, %2, %3;" : "=l"(d) : "l"(a), "l"(b), "l"(c));
    return d;
}

// ---------------- global min/max of img1 (single kernel, no init) ----------------

__device__ float2   g_part[MM_BLOCKS];
__device__ unsigned g_count = 0;        // returns to 0 at the end of every launch
__device__ float    g_mm[2];            // [0]=min, [1]=max

__global__ void minmax_k(const float4* __restrict__ x, int n4) {
    float lo =  3.402823466e38f;
    float hi = -3.402823466e38f;
    for (int i = blockIdx.x * blockDim.x + threadIdx.x; i < n4; i += gridDim.x * blockDim.x) {
        float4 v = x[i];
        lo = fminf(lo, fminf(fminf(v.x, v.y), fminf(v.z, v.w)));
        hi = fmaxf(hi, fmaxf(fmaxf(v.x, v.y), fmaxf(v.z, v.w)));
    }
    __shared__ float slo[8], shi[8];
    __shared__ int s_last;
    #pragma unroll
    for (int s = 16; s > 0; s >>= 1) {
        lo = fminf(lo, __shfl_xor_sync(0xFFFFFFFFu, lo, s));
        hi = fmaxf(hi, __shfl_xor_sync(0xFFFFFFFFu, hi, s));
    }
    int w = threadIdx.x >> 5, l = threadIdx.x & 31;
    if (l == 0) { slo[w] = lo; shi[w] = hi; }
    __syncthreads();
    if (threadIdx.x == 0) {
        int nw = blockDim.x >> 5;
        for (int i = 1; i < nw; i++) { lo = fminf(lo, slo[i]); hi = fmaxf(hi, shi[i]); }
        g_part[blockIdx.x] = make_float2(lo, hi);
        __threadfence();
        unsigned t = atomicAdd(&g_count, 1u);
        s_last = (t == (unsigned)(gridDim.x - 1)) ? 1 : 0;
    }
    __syncthreads();
    if (s_last) {
        __threadfence();
        lo =  3.402823466e38f;
        hi = -3.402823466e38f;
        for (int i = threadIdx.x; i < MM_BLOCKS; i += blockDim.x) {
            float2 p = g_part[i];
            lo = fminf(lo, p.x);
            hi = fmaxf(hi, p.y);
        }
        #pragma unroll
        for (int s = 16; s > 0; s >>= 1) {
            lo = fminf(lo, __shfl_xor_sync(0xFFFFFFFFu, lo, s));
            hi = fmaxf(hi, __shfl_xor_sync(0xFFFFFFFFu, hi, s));
        }
        if (l == 0) { slo[w] = lo; shi[w] = hi; }
        __syncthreads();
        if (threadIdx.x == 0) {
            int nw = blockDim.x >> 5;
            for (int i = 1; i < nw; i++) { lo = fminf(lo, slo[i]); hi = fmaxf(hi, shi[i]); }
            g_mm[0] = lo;
            g_mm[1] = hi;
            g_count = 0;          // reset for next launch (deterministic)
        }
    }
}

// ---------------- fused separable SSIM kernel ----------------
//
// One block = 64x16 output tile. smem = 37.1KB -> 6 blocks/SM.
// Field pairs travel as f32x2: pair01 = (mu1, mu2), pair23 = (xx+yy, xy).
// mid01/mid23 hold ONE float2 per logical column (index = column).
// Phase 1: cp.async 16B zfill halo load.
// Phase 2: vertical 11-tap conv, FFMA2 scatter into 2 float2 planes.
// Phase 3: horizontal 11-tap conv, streamed ulonglong2 loads + FFMA2, SSIM formula.

__global__ void __launch_bounds__(NTHREADS, 6)
ssim_kernel(const float* __restrict__ img1, const float* __restrict__ img2,
            float* __restrict__ out)
{
    extern __shared__ float smem[];
    float* s1 = smem;                          // IN_H * SSTRIDE floats
    float* s2 = smem + IN_H * SSTRIDE;
    ull* mid01 = reinterpret_cast<ull*>(smem + 2 * IN_H * SSTRIDE);   // TILE_H * S2STRIDE float2
    ull* mid23 = mid01 + TILE_H * S2STRIDE;

    const int bx = blockIdx.x, by = blockIdx.y, bz = blockIdx.z;
    const int tid = threadIdx.x;
    const size_t base = (size_t)bz * (IMG_H * IMG_W);
    const float* p1 = img1 + base;
    const float* p2 = img2 + base;

    // packed duplicated weights (same value in both lanes); compile-time indexed
    ull Wp[6];
    #pragma unroll
    for (int j = 0; j < 6; j++) {
        const float wv = (j == 0) ? Wc(0) : (j == 1) ? Wc(1) : (j == 2) ? Wc(2)
                       : (j == 3) ? Wc(3) : (j == 4) ? Wc(4) : Wc(5);
        Wp[j] = pack2(wv, wv);
    }

    // ---- Phase 1: cp.async halo load, zero-fill OOB granules ----
    const int gx_base = bx * TILE_W - 8;    // 16B-aligned; granules fully in/out
    const int gy_base = by * TILE_H - HALO;
    for (int idx = tid; idx < IN_H * 20; idx += NTHREADS) {
        int r  = idx / 20;
        int c4 = idx - r * 20;
        int gy = gy_base + r;
        int gx = gx_base + c4 * 4;
        bool ok = ((unsigned)gy < (unsigned)IMG_H) && ((unsigned)gx < (unsigned)IMG_W);
        int cgy = min(max(gy, 0), IMG_H - 1);
        int cgx = min(max(gx, 0), IMG_W - 4);
        const float* g1 = p1 + cgy * IMG_W + cgx;
        const float* g2 = p2 + cgy * IMG_W + cgx;
        unsigned d1 = (unsigned)__cvta_generic_to_shared(s1 + r * SSTRIDE + c4 * 4);
        unsigned d2 = (unsigned)__cvta_generic_to_shared(s2 + r * SSTRIDE + c4 * 4);
        int sz = ok ? 16 : 0;
        asm volatile("cp.async.cg.shared.global [%0], [%1], 16, %2;\n"
                     :: "r"(d1), "l"(g1), "r"(sz));
        asm volatile("cp.async.cg.shared.global [%0], [%1], 16, %2;\n"
                     :: "r"(d2), "l"(g2), "r"(sz));
    }
    asm volatile("cp.async.commit_group;\n");
    asm volatile("cp.async.wait_group 0;\n");
    __syncthreads();

    // ---- Phase 2: vertical conv, paired-field FFMA2 scatter ----
    for (int task = tid; task < IN_W * (TILE_H / 4); task += NTHREADS) {
        int c  = task % IN_W;              // logical column 0..73
        int j0 = (task / IN_W) * 4;
        const float* col1 = s1 + j0 * SSTRIDE + (c + 3);
        const float* col2 = s2 + j0 * SSTRIDE + (c + 3);

        ull A01[4], A23[4];
        #pragma unroll
        for (int m = 0; m < 4; m++) { A01[m] = 0ull; A23[m] = 0ull; }

        #pragma unroll
        for (int r = 0; r < 14; r++) {
            float x = col1[r * SSTRIDE];
            float y = col2[r * SSTRIDE];
            float xy   = x * y;
            float xxyy = fmaf(x, x, y * y);
            ull p01 = pack2(x, y);
            ull p23 = pack2(xxyy, xy);
            #pragma unroll
            for (int m = 0; m < 4; m++) {
                const int k = r - m;
                if (k >= 0 && k < 11) {         // compile-time resolved
                    A01[m] = fma2(p01, Wp[Widx(k)], A01[m]);
                    A23[m] = fma2(p23, Wp[Widx(k)], A23[m]);
                }
            }
        }
        #pragma unroll
        for (int m = 0; m < 4; m++) {
            int o = (j0 + m) * S2STRIDE + c;
            mid01[o] = A01[m];
            mid23[o] = A23[m];
        }
    }
    __syncthreads();

    // ---- Phase 3: horizontal conv (4 outputs/thread) + SSIM formula ----
    const int row = tid >> 4;          // 0..15
    const int c0  = (tid & 15) * 4;    // output col base 0,4,...,60; ALSO the
                                       // float2 load base (one float2 per column)

    float mu1v[4], mu2v[4], sqcv[4], xycv[4];

    // pair 0: (mu1, mu2)
    {
        ull acc[4] = {0ull, 0ull, 0ull, 0ull};
        const ulonglong2* p = reinterpret_cast<const ulonglong2*>(mid01 + row * S2STRIDE + c0);
        #pragma unroll
        for (int q = 0; q < 7; q++) {
            ulonglong2 u = p[q];
            #pragma unroll
            for (int h = 0; h < 2; h++) {
                const int j = 2 * q + h;
                const ull e = h ? u.y : u.x;
                #pragma unroll
                for (int i = 0; i < 4; i++) {
                    const int k = j - i;
                    if (k >= 0 && k < 11)
                        acc[i] = fma2(e, Wp[Widx(k)], acc[i]);
                }
            }
        }
        #pragma unroll
        for (int i = 0; i < 4; i++) unpack2(mu1v[i], mu2v[i], acc[i]);
    }
    // pair 1: (xx+yy, xy)
    {
        ull acc[4] = {0ull, 0ull, 0ull, 0ull};
        const ulonglong2* p = reinterpret_cast<const ulonglong2*>(mid23 + row * S2STRIDE + c0);
        #pragma unroll
        for (int q = 0; q < 7; q++) {
            ulonglong2 u = p[q];
            #pragma unroll
            for (int h = 0; h < 2; h++) {
                const int j = 2 * q + h;
                const ull e = h ? u.y : u.x;
                #pragma unroll
                for (int i = 0; i < 4; i++) {
                    const int k = j - i;
                    if (k >= 0 && k < 11)
                        acc[i] = fma2(e, Wp[Widx(k)], acc[i]);
                }
            }
        }
        #pragma unroll
        for (int i = 0; i < 4; i++) unpack2(sqcv[i], xycv[i], acc[i]);
    }

    // C1/C2 from global min/max
    float L = g_mm[1] - g_mm[0];
    if (L == 0.0f) L = 5.0f;
    const float c1v = 0.01f * L, c2v = 0.03f * L;
    const float C1 = c1v * c1v, C2 = c2v * c2v;

    float o4[4];
    #pragma unroll
    for (int i = 0; i < 4; i++) {
        float mu1 = mu1v[i], mu2 = mu2v[i];
        float mu1s = mu1 * mu1, mu2s = mu2 * mu2, m12 = mu1 * mu2;
        float sqsum = sqcv[i] - mu1s - mu2s;   // sigma1_sq + sigma2_sq
        float s12   = xycv[i] - m12;           // sigma12
        float num = (2.f * m12 + C1) * (2.f * s12 + C2);
        float den = (mu1s + mu2s + C1) * (sqsum + C2);
        o4[i] = __fdividef(num, den);
    }

    const int gy = by * TILE_H + row;
    const int gx = bx * TILE_W + c0;
    float4* po = reinterpret_cast<float4*>(out + base + gy * IMG_W + gx);
    po[0] = make_float4(o4[0], o4[1], o4[2], o4[3]);
}

// ---------------- launch ----------------

extern "C" void kernel_launch(void* const* d_in, const int* in_sizes, int n_in,
                              void* d_out, int out_size)
{
    const float* img1 = (const float*)d_in[0];
    const float* img2 = (const float*)d_in[1];
    float* out = (float*)d_out;
    const int n = in_sizes[0];
    const int batch = n / (IMG_H * IMG_W);

    const int smem_bytes = (2 * IN_H * SSTRIDE) * (int)sizeof(float)
                         + (2 * TILE_H * S2STRIDE) * (int)sizeof(ull);
    cudaFuncSetAttribute(ssim_kernel, cudaFuncAttributeMaxDynamicSharedMemorySize, smem_bytes);

    minmax_k<<<MM_BLOCKS, 256>>>((const float4*)img1, n / 4);

    dim3 grid(IMG_W / TILE_W, IMG_H / TILE_H, batch);
    ssim_kernel<<<grid, NTHREADS, smem_bytes>>>(img1, img2, out);
}